// round 15
// baseline (speedup 1.0000x reference)
#include <cuda_runtime.h>
#include <cuda_bf16.h>

#define NF   13776
#define KC   8
#define NT   256
#define RPB  16                   // receivers per block (2 per warp)
#define NBLK (NF / RPB)           // 861 blocks, exact
#define T1J  128                  // faces staged in smem; top-8 ~always inside
#define NCNT 32                   // spread completion counters
#define CPAD 64                   // 64 uints = 256B stride -> distinct LTS slices

// ---------------- scratch (device globals; no allocs) ----------------
__device__ float    g_partial[NBLK];
__device__ unsigned g_cnt[NCNT * CPAD];   // zero-initialized; finisher resets each replay

__device__ __forceinline__ float min3(float a, float b, float c) { return fminf(a, fminf(b, c)); }
__device__ __forceinline__ float max3(float a, float b, float c) { return fmaxf(a, fmaxf(b, c)); }

// ---------------- cone-field penalty (matches jnp fp32 math) ----------------
// SIGMA=0.5 -> r/SIGMA=2r, h/SIGMA=2h. POINT2PLANE=False, PENALIZE_OUTSIDE=True.
__device__ __forceinline__ float cone_pen(const float* __restrict__ s,
                                          const float* __restrict__ p) {
    float e0x = s[3] - s[0], e0y = s[4] - s[1], e0z = s[5] - s[2];
    float e1x = s[6] - s[0], e1y = s[7] - s[1], e1z = s[8] - s[2];
    float nx = e0y * e1z - e0z * e1y;
    float ny = e0z * e1x - e0x * e1z;
    float nz = e0x * e1y - e0y * e1x;
    float inv = 1.0f / (sqrtf(nx * nx + ny * ny + nz * nz) + 1e-8f);
    nx *= inv; ny *= inv; nz *= inv;
    float cx = (s[0] + s[3] + s[6]) * (1.0f / 3.0f);
    float cy = (s[1] + s[4] + s[7]) * (1.0f / 3.0f);
    float cz = (s[2] + s[5] + s[8]) * (1.0f / 3.0f);

    float acc = 0.0f;
#pragma unroll
    for (int v = 0; v < 3; ++v) {
        float ux = p[3 * v + 0] - cx;
        float uy = p[3 * v + 1] - cy;
        float uz = p[3 * v + 2] - cz;
        float h = ux * nx + uy * ny + uz * nz;
        float wx = ux - h * nx, wy = uy - h * ny, wz = uz - h * nz;
        float r = sqrtf(wx * wx + wy * wy + wz * wz);
        float radial = fmaxf(1.0f - 2.0f * r, 0.0f);
        float depth  = fmaxf(-h, 0.0f) + fmaxf(h, 0.0f) * __expf(-2.0f * h);
        float phi = radial * depth;
        acc += phi * phi;
    }
    return acc;
}

// ---------------- single fused kernel ----------------
__global__ void __launch_bounds__(NT)
fused_kernel(const float* __restrict__ verts,
             const int*   __restrict__ faces,
             float* __restrict__ out) {
    const int t    = threadIdx.x;
    const int lane = t & 31;
    const int w    = t >> 5;
    const int blockBase = blockIdx.x * RPB;

    __shared__ float4 sLo[T1J], sHi[T1J];       // .w = id0 / id1 (bits)
    __shared__ int    sId2[T1J];
    __shared__ float4 sTri[T1J][3];
    __shared__ float4 sRlo[RPB], sRhi[RPB];     // .w = id0 / id1 (bits)
    __shared__ int    sRid2[RPB];
    __shared__ float4 sRtri[RPB][3];
    __shared__ int    sPairs[RPB][KC];
    __shared__ float  ssum[NT / 32];

    // ---- prologue: stage chunk faces [0,T1J) + this block's receivers ----
    if (t < T1J) {
        int f = t;
        int i0 = faces[3 * f + 0], i1 = faces[3 * f + 1], i2 = faces[3 * f + 2];
        float ax = verts[3 * i0 + 0], ay = verts[3 * i0 + 1], az = verts[3 * i0 + 2];
        float bx = verts[3 * i1 + 0], by = verts[3 * i1 + 1], bz = verts[3 * i1 + 2];
        float cx = verts[3 * i2 + 0], cy = verts[3 * i2 + 1], cz = verts[3 * i2 + 2];
        sTri[f][0] = make_float4(ax, ay, az, 0.0f);
        sTri[f][1] = make_float4(bx, by, bz, 0.0f);
        sTri[f][2] = make_float4(cx, cy, cz, 0.0f);
        sLo[f] = make_float4(min3(ax, bx, cx), min3(ay, by, cy), min3(az, bz, cz),
                             __int_as_float(i0));
        sHi[f] = make_float4(max3(ax, bx, cx), max3(ay, by, cy), max3(az, bz, cz),
                             __int_as_float(i1));
        sId2[f] = i2;
    } else if (t < T1J + RPB) {
        int r = t - T1J;
        int f = blockBase + r;
        int i0 = faces[3 * f + 0], i1 = faces[3 * f + 1], i2 = faces[3 * f + 2];
        float ax = verts[3 * i0 + 0], ay = verts[3 * i0 + 1], az = verts[3 * i0 + 2];
        float bx = verts[3 * i1 + 0], by = verts[3 * i1 + 1], bz = verts[3 * i1 + 2];
        float cx = verts[3 * i2 + 0], cy = verts[3 * i2 + 1], cz = verts[3 * i2 + 2];
        sRtri[r][0] = make_float4(ax, ay, az, 0.0f);
        sRtri[r][1] = make_float4(bx, by, bz, 0.0f);
        sRtri[r][2] = make_float4(cx, cy, cz, 0.0f);
        sRlo[r] = make_float4(min3(ax, bx, cx), min3(ay, by, cy), min3(az, bz, cz),
                              __int_as_float(i0));
        sRhi[r] = make_float4(max3(ax, bx, cx), max3(ay, by, cy), max3(az, bz, cz),
                              __int_as_float(i1));
        sRid2[r] = i2;
    }
    __syncthreads();

    // ---- broad phase: warp ballot scan over smem, 2 receivers/warp ----
    const int rA = 2 * w, rB = 2 * w + 1;
    float4 rloA = sRlo[rA], rhiA = sRhi[rA];
    float4 rloB = sRlo[rB], rhiB = sRhi[rB];
    int a0 = __float_as_int(rloA.w), a1 = __float_as_int(rhiA.w), a2 = sRid2[rA];
    int b0 = __float_as_int(rloB.w), b1 = __float_as_int(rhiB.w), b2 = sRid2[rB];

    int cntA = 0, cntB = 0;
    for (int base = 0; base < T1J && (cntA < KC || cntB < KC); base += 32) {
        int j = base + lane;
        float4 jlo = sLo[j];
        float4 jhi = sHi[j];
        int j0 = __float_as_int(jlo.w);
        int j1 = __float_as_int(jhi.w);
        int j2 = sId2[j];

        bool okA = (rloA.x <= jhi.x) & (jlo.x <= rhiA.x) &
                   (rloA.y <= jhi.y) & (jlo.y <= rhiA.y) &
                   (rloA.z <= jhi.z) & (jlo.z <= rhiA.z);
        bool okB = (rloB.x <= jhi.x) & (jlo.x <= rhiB.x) &
                   (rloB.y <= jhi.y) & (jlo.y <= rhiB.y) &
                   (rloB.z <= jhi.z) & (jlo.z <= rhiB.z);
        if (okA) {
            bool sh = (a0 == j0) | (a0 == j1) | (a0 == j2) |
                      (a1 == j0) | (a1 == j1) | (a1 == j2) |
                      (a2 == j0) | (a2 == j1) | (a2 == j2);
            okA = !sh;
        }
        if (okB) {
            bool sh = (b0 == j0) | (b0 == j1) | (b0 == j2) |
                      (b1 == j0) | (b1 == j1) | (b1 == j2) |
                      (b2 == j0) | (b2 == j1) | (b2 == j2);
            okB = !sh;
        }
        unsigned mA = __ballot_sync(0xffffffffu, okA);
        unsigned mB = __ballot_sync(0xffffffffu, okB);
        unsigned lt = (1u << lane) - 1u;
        int rkA = __popc(mA & lt);
        int rkB = __popc(mB & lt);
        if (okA && (cntA + rkA) < KC) sPairs[rA][cntA + rkA] = j;
        if (okB && (cntB + rkB) < KC) sPairs[rB][cntB + rkB] = j;
        cntA = min(KC, cntA + __popc(mA));
        cntB = min(KC, cntB + __popc(mB));
    }

    // ---- exactness fallback (statistically ~never): continue into global ----
    if (cntA < KC || cntB < KC) {
#pragma unroll
        for (int sel = 0; sel < 2; ++sel) {
            int  rr  = sel ? rB : rA;
            int  cnt = sel ? cntB : cntA;
            if (cnt >= KC) continue;
            float4 rlo = sel ? rloB : rloA;
            float4 rhi = sel ? rhiB : rhiA;
            int q0 = sel ? b0 : a0, q1 = sel ? b1 : a1, q2 = sel ? b2 : a2;
            for (int base = T1J; base < NF && cnt < KC; base += 32) {
                int j = base + lane;
                bool ok = false;
                if (j < NF) {
                    int j0 = faces[3 * j + 0], j1 = faces[3 * j + 1], j2 = faces[3 * j + 2];
                    float ax = verts[3 * j0 + 0], ay = verts[3 * j0 + 1], az = verts[3 * j0 + 2];
                    float bx = verts[3 * j1 + 0], by = verts[3 * j1 + 1], bz = verts[3 * j1 + 2];
                    float cx = verts[3 * j2 + 0], cy = verts[3 * j2 + 1], cz = verts[3 * j2 + 2];
                    float jlx = min3(ax, bx, cx), jhx = max3(ax, bx, cx);
                    float jly = min3(ay, by, cy), jhy = max3(ay, by, cy);
                    float jlz = min3(az, bz, cz), jhz = max3(az, bz, cz);
                    ok = (rlo.x <= jhx) & (jlx <= rhi.x) &
                         (rlo.y <= jhy) & (jly <= rhi.y) &
                         (rlo.z <= jhz) & (jlz <= rhi.z);
                    if (ok) {
                        bool sh = (q0 == j0) | (q0 == j1) | (q0 == j2) |
                                  (q1 == j0) | (q1 == j1) | (q1 == j2) |
                                  (q2 == j0) | (q2 == j1) | (q2 == j2);
                        ok = !sh;
                    }
                }
                unsigned m = __ballot_sync(0xffffffffu, ok);
                int rk = __popc(m & ((1u << lane) - 1u));
                if (ok && (cnt + rk) < KC) sPairs[rr][cnt + rk] = j;
                cnt = min(KC, cnt + __popc(m));
            }
            if (sel) cntB = cnt; else cntA = cnt;
        }
    }

    if (lane < KC) {
        if (lane >= cntA) sPairs[rA][lane] = -1;
        if (lane >= cntB) sPairs[rB][lane] = -1;
    }
    __syncthreads();

    // ---- narrow phase: 256 tasks (r = t>>4, k = (t>>1)&7, dir = t&1) ----
    float acc = 0.0f;
    {
        int r = t >> 4;
        int k = (t >> 1) & 7;
        int j = sPairs[r][k];
        if (j >= 0) {
            float a[9], b[9];
            float4 v0 = sRtri[r][0], v1 = sRtri[r][1], v2 = sRtri[r][2];
            a[0] = v0.x; a[1] = v0.y; a[2] = v0.z;
            a[3] = v1.x; a[4] = v1.y; a[5] = v1.z;
            a[6] = v2.x; a[7] = v2.y; a[8] = v2.z;
            if (j < T1J) {
                float4 u0 = sTri[j][0], u1 = sTri[j][1], u2 = sTri[j][2];
                b[0] = u0.x; b[1] = u0.y; b[2] = u0.z;
                b[3] = u1.x; b[4] = u1.y; b[5] = u1.z;
                b[6] = u2.x; b[7] = u2.y; b[8] = u2.z;
            } else {  // fallback-found pair (rare): gather from global
                int j0 = faces[3 * j + 0], j1 = faces[3 * j + 1], j2 = faces[3 * j + 2];
                b[0] = verts[3 * j0 + 0]; b[1] = verts[3 * j0 + 1]; b[2] = verts[3 * j0 + 2];
                b[3] = verts[3 * j1 + 0]; b[4] = verts[3 * j1 + 1]; b[5] = verts[3 * j1 + 2];
                b[6] = verts[3 * j2 + 0]; b[7] = verts[3 * j2 + 1]; b[8] = verts[3 * j2 + 2];
            }
            acc = (t & 1) ? cone_pen(b, a) : cone_pen(a, b);
        }
    }

    // ---- block reduce (fixed order) -> partial ----
#pragma unroll
    for (int off = 16; off > 0; off >>= 1)
        acc += __shfl_down_sync(0xffffffffu, acc, off);
    if (lane == 0) ssum[w] = acc;
    __syncthreads();
    if (t == 0) {
        float v = 0.0f;
#pragma unroll
        for (int q = 0; q < NT / 32; ++q) v += ssum[q];
        g_partial[blockIdx.x] = v;
        __threadfence();
        // spread completion signal: 32 counters, 256B apart -> parallel LTS drains
        atomicAdd(&g_cnt[(blockIdx.x & (NCNT - 1)) * CPAD], 1u);   // result unused
    }

    // ---- designated finisher (block NBLK-1): poll, then fixed-order final sum ----
    if (blockIdx.x == NBLK - 1) {
        if (t == 0) {
            unsigned s;
            do {
                s = 0;
#pragma unroll
                for (int c = 0; c < NCNT; ++c)
                    s += *(volatile unsigned*)&g_cnt[c * CPAD];
                if (s < NBLK) __nanosleep(64);
            } while (s < NBLK);
#pragma unroll
            for (int c = 0; c < NCNT; ++c)
                g_cnt[c * CPAD] = 0;                 // reset for next graph replay
            __threadfence();                          // acquire partials
        }
        __syncthreads();

        float a = 0.0f;
        for (int b = t; b < NBLK; b += NT)           // fixed per-thread order
            a += g_partial[b];
#pragma unroll
        for (int off = 16; off > 0; off >>= 1)
            a += __shfl_down_sync(0xffffffffu, a, off);
        __shared__ float fsum[NT / 32];
        if (lane == 0) fsum[w] = a;
        __syncthreads();
        if (t == 0) {
            float v = 0.0f;
#pragma unroll
            for (int q = 0; q < NT / 32; ++q) v += fsum[q];
            out[0] = v;
        }
    }
}

// ---------------- launch ----------------
extern "C" void kernel_launch(void* const* d_in, const int* in_sizes, int n_in,
                              void* d_out, int out_size) {
    const float* verts = (const float*)d_in[0];
    const int*   faces = (const int*)d_in[1];
    float* out = (float*)d_out;

    fused_kernel<<<NBLK, NT>>>(verts, faces, out);
}